// round 13
// baseline (speedup 1.0000x reference)
#include <cuda_runtime.h>
#include <cuda_fp16.h>
#include <cstdint>

#define LL 2048
#define BB 32
#define HH 1024
#define MM (LL*BB)

// ---------------- device scratch ----------------
__device__ __half g_ah[(size_t)MM*HH];   // enc fp16, k-permuted within k16 windows
__device__ __half g_bh[(size_t)HH*HH];   // w1 fp16, same permutation
__device__ float2 g_pstP[(HH/2)*BB];     // (pst[2np][b], pst[2np+1][b]), bias folded
__device__ float g_score[MM];            // scores [l*B+b]
__device__ float g_cpart[32*BB*HH];      // context partials

// ---------------- PTX helpers ----------------
__device__ __forceinline__ uint32_t smem_u32(const void* p){
    uint32_t a;
    asm("{ .reg .u64 t; cvta.to.shared.u64 t, %1; cvt.u32.u64 %0, t; }" : "=r"(a) : "l"(p));
    return a;
}
__device__ __forceinline__ void cp16(uint32_t dst, const void* src){
    asm volatile("cp.async.ca.shared.global [%0], [%1], 16;" :: "r"(dst), "l"(src));
}
__device__ __forceinline__ void cp_commit(){ asm volatile("cp.async.commit_group;" ::: "memory"); }
__device__ __forceinline__ void cp_wait2(){ asm volatile("cp.async.wait_group 2;" ::: "memory"); }
__device__ __forceinline__ void cp_wait1(){ asm volatile("cp.async.wait_group 1;" ::: "memory"); }
__device__ __forceinline__ void cp_wait0(){ asm volatile("cp.async.wait_group 0;" ::: "memory"); }
__device__ __forceinline__ void mma_f16(float* c, uint32_t a0, uint32_t a1, uint32_t a2, uint32_t a3,
                                        uint32_t b0, uint32_t b1){
    asm volatile("mma.sync.aligned.m16n8k16.row.col.f32.f16.f16.f32 "
        "{%0,%1,%2,%3}, {%4,%5,%6,%7}, {%8,%9}, {%0,%1,%2,%3};"
        : "+f"(c[0]), "+f"(c[1]), "+f"(c[2]), "+f"(c[3])
        : "r"(a0), "r"(a1), "r"(a2), "r"(a3), "r"(b0), "r"(b1));
}
// pair tanh via f16x2 MUFU
__device__ __forceinline__ float2 tanh2(float x0, float x1){
    uint32_t h2, t2;
    asm("cvt.rn.f16x2.f32 %0, %1, %2;" : "=r"(h2) : "f"(x1), "f"(x0));
    asm("tanh.approx.f16x2 %0, %1;" : "=r"(t2) : "r"(h2));
    float r0, r1;
    asm("{.reg .b16 l, h;\n mov.b32 {l, h}, %2;\n cvt.f32.f16 %0, l;\n cvt.f32.f16 %1, h;}"
        : "=f"(r0), "=f"(r1) : "r"(t2));
    return make_float2(r0, r1);
}

// ---------------- SMEM layout ----------------
// k32 stage = [A0 4K][A1 4K][B0 4K][B1 4K] = 16384 B; 32B-row subtiles
// (same conflict-free phase layout as R8+). 4 stages.
#define STAGE_SZ 16384
#define OB       8192
#define O_RED    65536
#define SMEM_BYTES 74240     // 4*16384 + 128*17*4

// ---------------------------------------------------------------------------
// fp32 -> fp16, k-permuted within each k16 window:
// stored pos 4q+{0,1,2,3} <- orig k {2q, 2q+1, 2q+8, 2q+9}  (q = 0..3)
// Same permutation on A and B => sum over k unchanged.
// ---------------------------------------------------------------------------
__global__ void conv_half(const float* __restrict__ src, __half* __restrict__ dst){
    int t = blockIdx.x * 256 + threadIdx.x;
    int w = t & 63;             // k16 window
    int m = t >> 6;             // row
    const float* p = src + (size_t)m*HH + w*16;
    float4 x0 = *(const float4*)(p);
    float4 x1 = *(const float4*)(p + 4);
    float4 x2 = *(const float4*)(p + 8);
    float4 x3 = *(const float4*)(p + 12);
    float in[16] = {x0.x,x0.y,x0.z,x0.w, x1.x,x1.y,x1.z,x1.w,
                    x2.x,x2.y,x2.z,x2.w, x3.x,x3.y,x3.z,x3.w};
    uint32_t o[8];
    #pragma unroll
    for (int q = 0; q < 4; ++q){
        __half2 lo = __floats2half2_rn(in[2*q],     in[2*q + 1]);
        __half2 hi = __floats2half2_rn(in[2*q + 8], in[2*q + 9]);
        o[2*q]     = *(uint32_t*)&lo;
        o[2*q + 1] = *(uint32_t*)&hi;
    }
    uint4* d = (uint4*)(dst + (size_t)m*HH + w*16);
    d[0] = make_uint4(o[0], o[1], o[2], o[3]);
    d[1] = make_uint4(o[4], o[5], o[6], o[7]);
}

// ---------------------------------------------------------------------------
// pstP[np*32+b] = (pst[2np][b], pst[2np+1][b]); exact fp32
// ---------------------------------------------------------------------------
__global__ void pstT_kernel(const float* __restrict__ state, const float* __restrict__ w2,
                            const float* __restrict__ w1b, const float* __restrict__ w2b){
    int gw = (blockIdx.x * blockDim.x + threadIdx.x) >> 5;
    int lane = threadIdx.x & 31;
    if (gw >= (HH/2)*(BB/2)) return;
    int np = gw >> 4;
    int b0 = (gw & 15) * 2;
    int n0 = np * 2;
    const float* w0 = w2 + (size_t)n0 * HH;
    const float* w1r = w2 + (size_t)(n0+1) * HH;
    const float* s0 = state + b0*HH;
    const float* s1 = state + (b0+1)*HH;
    float a00=0.f, a01=0.f, a10=0.f, a11=0.f;
    #pragma unroll 4
    for (int h = lane; h < HH; h += 32){
        float x0 = s0[h], x1 = s1[h];
        float u = w0[h], w = w1r[h];
        a00 += u*x0; a01 += u*x1;
        a10 += w*x0; a11 += w*x1;
    }
    #pragma unroll
    for (int o = 16; o; o >>= 1){
        a00 += __shfl_xor_sync(~0u, a00, o);
        a01 += __shfl_xor_sync(~0u, a01, o);
        a10 += __shfl_xor_sync(~0u, a10, o);
        a11 += __shfl_xor_sync(~0u, a11, o);
    }
    if (lane == 0){
        float bias0 = w1b[n0] + w2b[n0];
        float bias1 = w1b[n0+1] + w2b[n0+1];
        g_pstP[np*BB + b0]   = make_float2(a00 + bias0, a10 + bias1);
        g_pstP[np*BB + b0+1] = make_float2(a01 + bias0, a11 + bias1);
    }
}

// ---------------------------------------------------------------------------
// cp.async one k32 stage: A 128x64B + B 128x64B as 2 k16 sub-tiles each.
// s encodes (nt, kt32): kt32 = s & 31, n0 = (s>>5)*128.
// ---------------------------------------------------------------------------
__device__ __forceinline__ void cp_stage(uint32_t sb, int m0, int s, int tid){
    int slot = s & 3;
    int kt = s & 31;
    int n0 = (s >> 5) << 7;
    uint32_t base = sb + slot*STAGE_SZ;
    int row = tid >> 1, c = tid & 1;
    const __half* asrc = g_ah + (size_t)(m0 + row)*HH + kt*32 + c*8;
    const __half* bsrc = g_bh + (size_t)(n0 + row)*HH + kt*32 + c*8;
    uint32_t adst = base + row*32 + c*16;
    uint32_t bdst = base + OB + row*32 + c*16;
    cp16(adst,        asrc);
    cp16(adst + 4096, asrc + 16);
    cp16(bdst,        bsrc);
    cp16(bdst + 4096, bsrc + 16);
    cp_commit();
}

// ---------------------------------------------------------------------------
// fused fp16 GEMM + tanh + v-dot
// CTA 128M x (8 x 128N); 8 warps (2M x 4N), warp tile 64x32, k32 macro-stages.
// Fine-grained interleave: per stage, [load h1][mma h0][advance: wait+sync,
// load next h0, cp prefetch][mma h1] -- crossbar and tensor overlap within
// and across warps instead of CTA-lockstep phases.
// ---------------------------------------------------------------------------
__global__ void __launch_bounds__(256, 2)
gemm_score(const float* __restrict__ v){
    extern __shared__ __align__(128) char smem[];
    uint32_t sb = smem_u32(smem);
    const int tid  = threadIdx.x;
    const int lane = tid & 31;
    const int wid  = tid >> 5;
    const int wm   = wid & 1;       // 2 M-bands of 64
    const int wn   = wid >> 1;      // 4 N-bands of 32
    const int m0   = blockIdx.x * 128;

    float* red = (float*)(smem + O_RED);
    for (int i = tid; i < 128*17; i += 256) red[i] = 0.f;
    __syncthreads();

    const int r0  = wm*64 + (lane>>2);    // A row base
    const int t8  = (lane&3)*8;           // byte offset of lane's 4 halves
    const int nb0 = wn*32 + (lane>>2);    // B row base

    float acc[4][4][4];
    #pragma unroll
    for (int a = 0; a < 4; a++)
        #pragma unroll
        for (int b = 0; b < 4; b++)
            #pragma unroll
            for (int c = 0; c < 4; c++) acc[a][b][c] = 0.f;

    cp_stage(sb, m0, 0, tid);
    cp_stage(sb, m0, 1, tid);
    cp_stage(sb, m0, 2, tid);

    // fragment double buffers: buf0 = current h0, buf1 = current h1
    uint2 Bu0[4], Bu1[4], Alo0[4], Ahi0[4], Alo1[4], Ahi1[4];

    cp_wait2();
    __syncthreads();
    {   // prologue: load h0 fragments of stage 0
        const char* sA = smem;            // slot 0, half 0
        const char* sB = smem + OB;
        #pragma unroll
        for (int nf = 0; nf < 4; ++nf)
            Bu0[nf] = *(const uint2*)(sB + (nb0 + nf*8)*32 + t8);
        #pragma unroll
        for (int mf = 0; mf < 4; ++mf){
            Alo0[mf] = *(const uint2*)(sA + (r0 + mf*16    )*32 + t8);
            Ahi0[mf] = *(const uint2*)(sA + (r0 + mf*16 + 8)*32 + t8);
        }
    }

    for (int s = 0; s < 256; ++s){
        const char* st = smem + (s&3)*STAGE_SZ;

        // ---- load h1 fragments (overlaps other warps' MMA bursts) ----
        {
            const char* sA = st + 4096;
            const char* sB = st + OB + 4096;
            #pragma unroll
            for (int nf = 0; nf < 4; ++nf)
                Bu1[nf] = *(const uint2*)(sB + (nb0 + nf*8)*32 + t8);
            #pragma unroll
            for (int mf = 0; mf < 4; ++mf){
                Alo1[mf] = *(const uint2*)(sA + (r0 + mf*16    )*32 + t8);
                Ahi1[mf] = *(const uint2*)(sA + (r0 + mf*16 + 8)*32 + t8);
            }
        }

        // ---- 16 MMAs on h0 (hides h1 load latency) ----
        #pragma unroll
        for (int mf = 0; mf < 4; ++mf)
            #pragma unroll
            for (int nf = 0; nf < 4; ++nf)
                mma_f16(acc[mf][nf], Alo0[mf].x, Ahi0[mf].x, Alo0[mf].y, Ahi0[mf].y,
                        Bu0[nf].x, Bu0[nf].y);

        // ---- advance pipeline: stage s+1 readiness, refill buf0, prefetch ----
        if (s < 255){
            if (s < 253) cp_wait1(); else cp_wait0();
            __syncthreads();
            const char* stn = smem + ((s+1)&3)*STAGE_SZ;
            const char* sA = stn;
            const char* sB = stn + OB;
            #pragma unroll
            for (int nf = 0; nf < 4; ++nf)
                Bu0[nf] = *(const uint2*)(sB + (nb0 + nf*8)*32 + t8);
            #pragma unroll
            for (int mf = 0; mf < 4; ++mf){
                Alo0[mf] = *(const uint2*)(sA + (r0 + mf*16    )*32 + t8);
                Ahi0[mf] = *(const uint2*)(sA + (r0 + mf*16 + 8)*32 + t8);
            }
            if (s + 3 < 256) cp_stage(sb, m0, s + 3, tid);
        }

        // ---- 16 MMAs on h1 (hides buf0 refill latency) ----
        #pragma unroll
        for (int mf = 0; mf < 4; ++mf)
            #pragma unroll
            for (int nf = 0; nf < 4; ++nf)
                mma_f16(acc[mf][nf], Alo1[mf].x, Ahi1[mf].x, Alo1[mf].y, Ahi1[mf].y,
                        Bu1[nf].x, Bu1[nf].y);

        if ((s & 31) == 31){
            // epilogue for nt = s>>5 (N columns n0t..n0t+127)
            int n0t = (s >> 5) << 7;
            int npb = (n0t >> 1) + wn*16 + (lane&3);
            float2 vp[4], pstr[4][4];                   // pstr[bg][nf]
            #pragma unroll
            for (int nf = 0; nf < 4; ++nf){
                int np = npb + nf*4;
                vp[nf] = *(const float2*)(v + np*2);
                #pragma unroll
                for (int bg = 0; bg < 4; ++bg){
                    int b = (lane>>2) + bg*8;
                    pstr[bg][nf] = __ldg(&g_pstP[np*BB + b]);
                }
            }
            #pragma unroll
            for (int mf = 0; mf < 4; ++mf){
                #pragma unroll
                for (int half = 0; half < 2; ++half){
                    int row = wm*64 + mf*16 + (lane>>2) + half*8;
                    int bg  = (mf&1)*2 + half;
                    float sacc = 0.f;
                    #pragma unroll
                    for (int nf = 0; nf < 4; ++nf){
                        float x0 = acc[mf][nf][half*2 + 0] + pstr[bg][nf].x;
                        float x1 = acc[mf][nf][half*2 + 1] + pstr[bg][nf].y;
                        float2 t = tanh2(x0, x1);
                        sacc = fmaf(vp[nf].x, t.x, fmaf(vp[nf].y, t.y, sacc));
                    }
                    red[row*17 + wn*4 + (lane&3)] += sacc;
                }
            }
            #pragma unroll
            for (int a = 0; a < 4; a++)
                #pragma unroll
                for (int b = 0; b < 4; b++)
                    #pragma unroll
                    for (int c = 0; c < 4; c++) acc[a][b][c] = 0.f;
        }
    }

    __syncthreads();
    if (tid < 128){
        const float* r = red + tid*17;
        float s = 0.f;
        #pragma unroll
        for (int j = 0; j < 16; ++j) s += r[j];
        g_score[m0 + tid] = s;
    }
}

// ---------------------------------------------------------------------------
// softmax over L per batch column b; weights -> out + B*H, layout [l*B+b]
// ---------------------------------------------------------------------------
__global__ void softmax_kernel(float* __restrict__ out){
    __shared__ float sdata[256];
    int b = blockIdx.x;
    int tid = threadIdx.x;

    float mx = -1e30f;
    for (int l = tid; l < LL; l += 256) mx = fmaxf(mx, g_score[l*BB + b]);
    sdata[tid] = mx; __syncthreads();
    for (int s = 128; s > 0; s >>= 1){ if (tid < s) sdata[tid] = fmaxf(sdata[tid], sdata[tid+s]); __syncthreads(); }
    mx = sdata[0]; __syncthreads();

    float sum = 0.f;
    for (int l = tid; l < LL; l += 256) sum += __expf(g_score[l*BB + b] - mx);
    sdata[tid] = sum; __syncthreads();
    for (int s = 128; s > 0; s >>= 1){ if (tid < s) sdata[tid] += sdata[tid+s]; __syncthreads(); }
    float inv = 1.f / sdata[0];

    float* w = out + BB*HH;
    for (int l = tid; l < LL; l += 256)
        w[l*BB + b] = __expf(g_score[l*BB + b] - mx) * inv;
}

// ---------------------------------------------------------------------------
// context: 32-way L-split partials, then reduce; float4 over H
// ---------------------------------------------------------------------------
__global__ void ctx_part(const float* __restrict__ enc, const float* __restrict__ wts){
    int s = blockIdx.x;
    int b = blockIdx.y;
    int t = threadIdx.x;
    const float4* e = (const float4*)enc;
    float4 acc = make_float4(0.f, 0.f, 0.f, 0.f);
    int l0 = s * 64;
    #pragma unroll 4
    for (int l = 0; l < 64; ++l){
        float w = wts[(l0 + l)*BB + b];
        float4 x = e[((size_t)(l0 + l)*BB + b)*256 + t];
        acc.x += w*x.x; acc.y += w*x.y; acc.z += w*x.z; acc.w += w*x.w;
    }
    ((float4*)g_cpart)[((size_t)s*BB + b)*256 + t] = acc;
}
__global__ void ctx_reduce(float* __restrict__ out){
    int b = blockIdx.x;
    int t = threadIdx.x;
    float4 acc = make_float4(0.f, 0.f, 0.f, 0.f);
    #pragma unroll
    for (int s = 0; s < 32; ++s){
        float4 x = ((const float4*)g_cpart)[((size_t)s*BB + b)*256 + t];
        acc.x += x.x; acc.y += x.y; acc.z += x.z; acc.w += x.w;
    }
    ((float4*)out)[b*256 + t] = acc;
}

// ---------------------------------------------------------------------------
// launch: out = [context (B*H) | att_weights (L*B)]
// ---------------------------------------------------------------------------
extern "C" void kernel_launch(void* const* d_in, const int* in_sizes, int n_in,
                              void* d_out, int out_size) {
    const float* enc = (const float*)d_in[0];
    const float* lds = (const float*)d_in[1];   // state = first B*H floats
    const float* w1w = (const float*)d_in[2];
    const float* w1b = (const float*)d_in[3];
    const float* w2w = (const float*)d_in[4];
    const float* w2b = (const float*)d_in[5];
    const float* vw  = (const float*)d_in[6];
    // v_b cancels under softmax

    float* out = (float*)d_out;

    static bool attr_set = false;
    if (!attr_set){
        cudaFuncSetAttribute(gemm_score, cudaFuncAttributeMaxDynamicSharedMemorySize, SMEM_BYTES);
        attr_set = true;
    }

    __half *ah, *bh;
    cudaGetSymbolAddress((void**)&ah, g_ah);
    cudaGetSymbolAddress((void**)&bh, g_bh);

    conv_half<<<MM*64/256, 256>>>(enc, ah);
    conv_half<<<HH*64/256, 256>>>(w1w, bh);
    pstT_kernel<<<(HH/2)*(BB/2)/8, 256>>>(lds, w2w, w1b, w2b);
    gemm_score<<<MM/128, 256, SMEM_BYTES>>>(vw);
    softmax_kernel<<<BB, 256>>>(out);
    ctx_part<<<dim3(32, BB), 256>>>(enc, out + BB*HH);
    ctx_reduce<<<BB, 256>>>(out);
}

// round 14
// speedup vs baseline: 1.6113x; 1.6113x over previous
#include <cuda_runtime.h>
#include <cuda_fp16.h>
#include <cstdint>

#define LL 2048
#define BB 32
#define HH 1024
#define MM (LL*BB)

// ---------------- device scratch ----------------
__device__ __half g_ah[(size_t)MM*HH];   // enc fp16 (standard layout)
__device__ __half g_bh[(size_t)HH*HH];   // w1 fp16
__device__ float2 g_pstP[(HH/2)*BB];     // (pst[2np][b], pst[2np+1][b]), bias folded
__device__ float g_score[MM];            // scores [l*B+b]
__device__ float g_cpart[32*BB*HH];      // context partials

// ---------------- PTX helpers ----------------
__device__ __forceinline__ uint32_t smem_u32(const void* p){
    uint32_t a;
    asm("{ .reg .u64 t; cvta.to.shared.u64 t, %1; cvt.u32.u64 %0, t; }" : "=r"(a) : "l"(p));
    return a;
}
__device__ __forceinline__ void cp16(uint32_t dst, const void* src){
    asm volatile("cp.async.ca.shared.global [%0], [%1], 16;" :: "r"(dst), "l"(src));
}
__device__ __forceinline__ void cp_commit(){ asm volatile("cp.async.commit_group;" ::: "memory"); }
__device__ __forceinline__ void cp_wait2(){ asm volatile("cp.async.wait_group 2;" ::: "memory"); }
__device__ __forceinline__ void cp_wait0(){ asm volatile("cp.async.wait_group 0;" ::: "memory"); }
__device__ __forceinline__ void ldsm4(uint32_t* r, uint32_t addr){
    asm volatile("ldmatrix.sync.aligned.m8n8.x4.shared.b16 {%0,%1,%2,%3}, [%4];"
        : "=r"(r[0]), "=r"(r[1]), "=r"(r[2]), "=r"(r[3]) : "r"(addr));
}
__device__ __forceinline__ void mma_f16(float* c, uint32_t a0, uint32_t a1, uint32_t a2, uint32_t a3,
                                        uint32_t b0, uint32_t b1){
    asm volatile("mma.sync.aligned.m16n8k16.row.col.f32.f16.f16.f32 "
        "{%0,%1,%2,%3}, {%4,%5,%6,%7}, {%8,%9}, {%0,%1,%2,%3};"
        : "+f"(c[0]), "+f"(c[1]), "+f"(c[2]), "+f"(c[3])
        : "r"(a0), "r"(a1), "r"(a2), "r"(a3), "r"(b0), "r"(b1));
}
// pair tanh via f16x2 MUFU
__device__ __forceinline__ float2 tanh2(float x0, float x1){
    uint32_t h2, t2;
    asm("cvt.rn.f16x2.f32 %0, %1, %2;" : "=r"(h2) : "f"(x1), "f"(x0));
    asm("tanh.approx.f16x2 %0, %1;" : "=r"(t2) : "r"(h2));
    float r0, r1;
    asm("{.reg .b16 l, h;\n mov.b32 {l, h}, %2;\n cvt.f32.f16 %0, l;\n cvt.f32.f16 %1, h;}"
        : "=f"(r0), "=f"(r1) : "r"(t2));
    return make_float2(r0, r1);
}

// ---------------- SMEM layout ----------------
// k32 stage = [A0 4K][A1 4K][B0 4K][B1 4K] = 16384 B; 32B-row subtiles. 4 stages.
#define STAGE_SZ 16384
#define OB       8192
#define O_RED    65536
#define SMEM_BYTES 74240     // 4*16384 + 128*17*4

// ---------------------------------------------------------------------------
// fp32 -> fp16, straight convert (ldmatrix consumes standard [row][k] layout)
// One thread per (row, k16 window): read 16 floats, write 32 bytes.
// ---------------------------------------------------------------------------
__global__ void conv_half(const float* __restrict__ src, __half* __restrict__ dst){
    int t = blockIdx.x * 256 + threadIdx.x;
    int w = t & 63;             // k16 window
    int m = t >> 6;             // row
    const float* p = src + (size_t)m*HH + w*16;
    float4 x0 = *(const float4*)(p);
    float4 x1 = *(const float4*)(p + 4);
    float4 x2 = *(const float4*)(p + 8);
    float4 x3 = *(const float4*)(p + 12);
    uint32_t o[8];
    __half2 h;
    h = __floats2half2_rn(x0.x, x0.y); o[0] = *(uint32_t*)&h;
    h = __floats2half2_rn(x0.z, x0.w); o[1] = *(uint32_t*)&h;
    h = __floats2half2_rn(x1.x, x1.y); o[2] = *(uint32_t*)&h;
    h = __floats2half2_rn(x1.z, x1.w); o[3] = *(uint32_t*)&h;
    h = __floats2half2_rn(x2.x, x2.y); o[4] = *(uint32_t*)&h;
    h = __floats2half2_rn(x2.z, x2.w); o[5] = *(uint32_t*)&h;
    h = __floats2half2_rn(x3.x, x3.y); o[6] = *(uint32_t*)&h;
    h = __floats2half2_rn(x3.z, x3.w); o[7] = *(uint32_t*)&h;
    uint4* d = (uint4*)(dst + (size_t)m*HH + w*16);
    d[0] = make_uint4(o[0], o[1], o[2], o[3]);
    d[1] = make_uint4(o[4], o[5], o[6], o[7]);
}

// ---------------------------------------------------------------------------
// pstP[np*32+b] = (pst[2np][b], pst[2np+1][b]); exact fp32
// ---------------------------------------------------------------------------
__global__ void pstT_kernel(const float* __restrict__ state, const float* __restrict__ w2,
                            const float* __restrict__ w1b, const float* __restrict__ w2b){
    int gw = (blockIdx.x * blockDim.x + threadIdx.x) >> 5;
    int lane = threadIdx.x & 31;
    if (gw >= (HH/2)*(BB/2)) return;
    int np = gw >> 4;
    int b0 = (gw & 15) * 2;
    int n0 = np * 2;
    const float* w0 = w2 + (size_t)n0 * HH;
    const float* w1r = w2 + (size_t)(n0+1) * HH;
    const float* s0 = state + b0*HH;
    const float* s1 = state + (b0+1)*HH;
    float a00=0.f, a01=0.f, a10=0.f, a11=0.f;
    #pragma unroll 4
    for (int h = lane; h < HH; h += 32){
        float x0 = s0[h], x1 = s1[h];
        float u = w0[h], w = w1r[h];
        a00 += u*x0; a01 += u*x1;
        a10 += w*x0; a11 += w*x1;
    }
    #pragma unroll
    for (int o = 16; o; o >>= 1){
        a00 += __shfl_xor_sync(~0u, a00, o);
        a01 += __shfl_xor_sync(~0u, a01, o);
        a10 += __shfl_xor_sync(~0u, a10, o);
        a11 += __shfl_xor_sync(~0u, a11, o);
    }
    if (lane == 0){
        float bias0 = w1b[n0] + w2b[n0];
        float bias1 = w1b[n0+1] + w2b[n0+1];
        g_pstP[np*BB + b0]   = make_float2(a00 + bias0, a10 + bias1);
        g_pstP[np*BB + b0+1] = make_float2(a01 + bias0, a11 + bias1);
    }
}

// ---------------------------------------------------------------------------
// cp.async one k32 stage: A 128x64B + B 128x64B as 2 k16 sub-tiles each.
// ---------------------------------------------------------------------------
__device__ __forceinline__ void cp_stage(uint32_t sb, int m0, int s, int tid){
    int slot = s & 3;
    int kt = s & 31;
    int n0 = (s >> 5) << 7;
    uint32_t base = sb + slot*STAGE_SZ;
    int row = tid >> 1, c = tid & 1;
    const __half* asrc = g_ah + (size_t)(m0 + row)*HH + kt*32 + c*8;
    const __half* bsrc = g_bh + (size_t)(n0 + row)*HH + kt*32 + c*8;
    uint32_t adst = base + row*32 + c*16;
    uint32_t bdst = base + OB + row*32 + c*16;
    cp16(adst,        asrc);
    cp16(adst + 4096, asrc + 16);
    cp16(bdst,        bsrc);
    cp16(bdst + 4096, bsrc + 16);
    cp_commit();
}

// ---------------------------------------------------------------------------
// fused fp16 GEMM + tanh + v-dot
// CTA 128M x (8 x 128N); 8 warps (2M x 4N), warp tile 64x32, k32 macro-stages.
// Fragments via ldmatrix.x4: 6 LDSM per warp-k16 (was 12 LDS.64 + addressing).
// Per-lane ldmatrix addresses computed once; both halves loaded then 32 MMAs.
// ---------------------------------------------------------------------------
__global__ void __launch_bounds__(256, 2)
gemm_score(const float* __restrict__ v){
    extern __shared__ __align__(128) char smem[];
    uint32_t sb = smem_u32(smem);
    const int tid  = threadIdx.x;
    const int lane = tid & 31;
    const int wid  = tid >> 5;
    const int wm   = wid & 1;       // 2 M-bands of 64
    const int wn   = wid >> 1;      // 4 N-bands of 32
    const int m0   = blockIdx.x * 128;
    const int hsel = wid & 1;       // stagger: odd warps do half1 first

    float* red = (float*)(smem + O_RED);
    for (int i = tid; i < 128*17; i += 256) red[i] = 0.f;
    __syncthreads();

    // per-lane ldmatrix byte offsets (within a 4KB subtile)
    // A (16x16 tile at row base wm*64 + mf*16): lanes 0-15 rows, 16-31 k-hi
    const uint32_t aoff = (uint32_t)(wm*2048 + (lane&15)*32 + (lane>>4)*16);
    // B (two 8n tiles per ldsm4): group g=lane>>3: nrow=(lane&7)+(g>>1)*8, ncol=(g&1)*16
    const uint32_t boff = (uint32_t)(wn*1024 + ((lane&7) + ((lane>>4)&1)*8)*32 + (((lane>>3)&1))*16);

    float acc[4][4][4];
    #pragma unroll
    for (int a = 0; a < 4; a++)
        #pragma unroll
        for (int b = 0; b < 4; b++)
            #pragma unroll
            for (int c = 0; c < 4; c++) acc[a][b][c] = 0.f;

    cp_stage(sb, m0, 0, tid);
    cp_stage(sb, m0, 1, tid);
    cp_stage(sb, m0, 2, tid);

    for (int s = 0; s < 256; ++s){
        if (s < 253) cp_wait2(); else cp_wait0();
        __syncthreads();
        if (s + 3 < 256) cp_stage(sb, m0, s + 3, tid);

        uint32_t st = sb + (s&3)*STAGE_SZ;
        uint32_t sA0 = st + hsel*4096;
        uint32_t sB0 = st + OB + hsel*4096;
        uint32_t sA1 = st + (hsel^1)*4096;
        uint32_t sB1 = st + OB + (hsel^1)*4096;

        // ---- load ALL fragments for both halves via ldmatrix ----
        uint32_t A0[4][4], A1[4][4], B0[8], B1[8];
        ldsm4(B0,     sB0 + boff);         // nf0 b0,b1, nf1 b0,b1
        ldsm4(B0 + 4, sB0 + boff + 512);   // nf2, nf3
        #pragma unroll
        for (int mf = 0; mf < 4; ++mf)
            ldsm4(A0[mf], sA0 + aoff + mf*512);
        ldsm4(B1,     sB1 + boff);
        ldsm4(B1 + 4, sB1 + boff + 512);
        #pragma unroll
        for (int mf = 0; mf < 4; ++mf)
            ldsm4(A1[mf], sA1 + aoff + mf*512);

        // ---- 32 back-to-back MMAs ----
        #pragma unroll
        for (int mf = 0; mf < 4; ++mf)
            #pragma unroll
            for (int nf = 0; nf < 4; ++nf)
                mma_f16(acc[mf][nf], A0[mf][0], A0[mf][1], A0[mf][2], A0[mf][3],
                        B0[nf*2], B0[nf*2+1]);
        #pragma unroll
        for (int mf = 0; mf < 4; ++mf)
            #pragma unroll
            for (int nf = 0; nf < 4; ++nf)
                mma_f16(acc[mf][nf], A1[mf][0], A1[mf][1], A1[mf][2], A1[mf][3],
                        B1[nf*2], B1[nf*2+1]);

        if ((s & 31) == 31){
            // epilogue for nt = s>>5 (N columns n0t..n0t+127)
            int n0t = (s >> 5) << 7;
            int npb = (n0t >> 1) + wn*16 + (lane&3);
            float2 vp[4], pstr[4][4];                   // pstr[bg][nf]
            #pragma unroll
            for (int nf = 0; nf < 4; ++nf){
                int np = npb + nf*4;
                vp[nf] = *(const float2*)(v + np*2);
                #pragma unroll
                for (int bg = 0; bg < 4; ++bg){
                    int b = (lane>>2) + bg*8;
                    pstr[bg][nf] = __ldg(&g_pstP[np*BB + b]);
                }
            }
            #pragma unroll
            for (int mf = 0; mf < 4; ++mf){
                #pragma unroll
                for (int half = 0; half < 2; ++half){
                    int row = wm*64 + mf*16 + (lane>>2) + half*8;
                    int bg  = (mf&1)*2 + half;
                    float sacc = 0.f;
                    #pragma unroll
                    for (int nf = 0; nf < 4; ++nf){
                        float x0 = acc[mf][nf][half*2 + 0] + pstr[bg][nf].x;
                        float x1 = acc[mf][nf][half*2 + 1] + pstr[bg][nf].y;
                        float2 t = tanh2(x0, x1);
                        sacc = fmaf(vp[nf].x, t.x, fmaf(vp[nf].y, t.y, sacc));
                    }
                    red[row*17 + wn*4 + (lane&3)] += sacc;
                }
            }
            #pragma unroll
            for (int a = 0; a < 4; a++)
                #pragma unroll
                for (int b = 0; b < 4; b++)
                    #pragma unroll
                    for (int c = 0; c < 4; c++) acc[a][b][c] = 0.f;
        }
    }

    __syncthreads();
    if (tid < 128){
        const float* r = red + tid*17;
        float s = 0.f;
        #pragma unroll
        for (int j = 0; j < 16; ++j) s += r[j];
        g_score[m0 + tid] = s;
    }
}

// ---------------------------------------------------------------------------
// softmax over L per batch column b; weights -> out + B*H, layout [l*B+b]
// ---------------------------------------------------------------------------
__global__ void softmax_kernel(float* __restrict__ out){
    __shared__ float sdata[256];
    int b = blockIdx.x;
    int tid = threadIdx.x;

    float mx = -1e30f;
    for (int l = tid; l < LL; l += 256) mx = fmaxf(mx, g_score[l*BB + b]);
    sdata[tid] = mx; __syncthreads();
    for (int s = 128; s > 0; s >>= 1){ if (tid < s) sdata[tid] = fmaxf(sdata[tid], sdata[tid+s]); __syncthreads(); }
    mx = sdata[0]; __syncthreads();

    float sum = 0.f;
    for (int l = tid; l < LL; l += 256) sum += __expf(g_score[l*BB + b] - mx);
    sdata[tid] = sum; __syncthreads();
    for (int s = 128; s > 0; s >>= 1){ if (tid < s) sdata[tid] += sdata[tid+s]; __syncthreads(); }
    float inv = 1.f / sdata[0];

    float* w = out + BB*HH;
    for (int l = tid; l < LL; l += 256)
        w[l*BB + b] = __expf(g_score[l*BB + b] - mx) * inv;
}

// ---------------------------------------------------------------------------
// context: 32-way L-split partials, then reduce; float4 over H
// ---------------------------------------------------------------------------
__global__ void ctx_part(const float* __restrict__ enc, const float* __restrict__ wts){
    int s = blockIdx.x;
    int b = blockIdx.y;
    int t = threadIdx.x;
    const float4* e = (const float4*)enc;
    float4 acc = make_float4(0.f, 0.f, 0.f, 0.f);
    int l0 = s * 64;
    #pragma unroll 4
    for (int l = 0; l < 64; ++l){
        float w = wts[(l0 + l)*BB + b];
        float4 x = e[((size_t)(l0 + l)*BB + b)*256 + t];
        acc.x += w*x.x; acc.y += w*x.y; acc.z += w*x.z; acc.w += w*x.w;
    }
    ((float4*)g_cpart)[((size_t)s*BB + b)*256 + t] = acc;
}
__global__ void ctx_reduce(float* __restrict__ out){
    int b = blockIdx.x;
    int t = threadIdx.x;
    float4 acc = make_float4(0.f, 0.f, 0.f, 0.f);
    #pragma unroll
    for (int s = 0; s < 32; ++s){
        float4 x = ((const float4*)g_cpart)[((size_t)s*BB + b)*256 + t];
        acc.x += x.x; acc.y += x.y; acc.z += x.z; acc.w += x.w;
    }
    ((float4*)out)[b*256 + t] = acc;
}

// ---------------------------------------------------------------------------
// launch: out = [context (B*H) | att_weights (L*B)]
// ---------------------------------------------------------------------------
extern "C" void kernel_launch(void* const* d_in, const int* in_sizes, int n_in,
                              void* d_out, int out_size) {
    const float* enc = (const float*)d_in[0];
    const float* lds = (const float*)d_in[1];   // state = first B*H floats
    const float* w1w = (const float*)d_in[2];
    const float* w1b = (const float*)d_in[3];
    const float* w2w = (const float*)d_in[4];
    const float* w2b = (const float*)d_in[5];
    const float* vw  = (const float*)d_in[6];
    // v_b cancels under softmax

    float* out = (float*)d_out;

    static bool attr_set = false;
    if (!attr_set){
        cudaFuncSetAttribute(gemm_score, cudaFuncAttributeMaxDynamicSharedMemorySize, SMEM_BYTES);
        attr_set = true;
    }

    __half *ah, *bh;
    cudaGetSymbolAddress((void**)&ah, g_ah);
    cudaGetSymbolAddress((void**)&bh, g_bh);

    conv_half<<<MM*64/256, 256>>>(enc, ah);
    conv_half<<<HH*64/256, 256>>>(w1w, bh);
    pstT_kernel<<<(HH/2)*(BB/2)/8, 256>>>(lds, w2w, w1b, w2b);
    gemm_score<<<MM/128, 256, SMEM_BYTES>>>(vw);
    softmax_kernel<<<BB, 256>>>(out);
    ctx_part<<<dim3(32, BB), 256>>>(enc, out + BB*HH);
    ctx_reduce<<<BB, 256>>>(out);
}

// round 15
// speedup vs baseline: 1.9612x; 1.2172x over previous
#include <cuda_runtime.h>
#include <cuda_fp16.h>
#include <cstdint>

#define LL 2048
#define BB 32
#define HH 1024
#define MM (LL*BB)

// ---------------- device scratch ----------------
__device__ __half g_ah[(size_t)MM*HH];   // enc fp16 (standard layout)
__device__ __half g_bh[(size_t)HH*HH];   // w1 fp16
__device__ float2 g_pstP[(HH/2)*BB];     // (pst[2np][b], pst[2np+1][b]), bias folded
__device__ float g_score[MM];            // scores [l*B+b]
__device__ float g_cpart[32*BB*HH];      // context partials

// ---------------- PTX helpers ----------------
__device__ __forceinline__ uint32_t smem_u32(const void* p){
    uint32_t a;
    asm("{ .reg .u64 t; cvta.to.shared.u64 t, %1; cvt.u32.u64 %0, t; }" : "=r"(a) : "l"(p));
    return a;
}
__device__ __forceinline__ void cp16(uint32_t dst, const void* src){
    asm volatile("cp.async.ca.shared.global [%0], [%1], 16;" :: "r"(dst), "l"(src));
}
__device__ __forceinline__ void cp_commit(){ asm volatile("cp.async.commit_group;" ::: "memory"); }
__device__ __forceinline__ void cp_wait2(){ asm volatile("cp.async.wait_group 2;" ::: "memory"); }
__device__ __forceinline__ void cp_wait0(){ asm volatile("cp.async.wait_group 0;" ::: "memory"); }
__device__ __forceinline__ void ldsm4(uint32_t* r, uint32_t addr){
    asm volatile("ldmatrix.sync.aligned.m8n8.x4.shared.b16 {%0,%1,%2,%3}, [%4];"
        : "=r"(r[0]), "=r"(r[1]), "=r"(r[2]), "=r"(r[3]) : "r"(addr));
}
__device__ __forceinline__ void mma_f16(float* c, uint32_t a0, uint32_t a1, uint32_t a2, uint32_t a3,
                                        uint32_t b0, uint32_t b1){
    asm volatile("mma.sync.aligned.m16n8k16.row.col.f32.f16.f16.f32 "
        "{%0,%1,%2,%3}, {%4,%5,%6,%7}, {%8,%9}, {%0,%1,%2,%3};"
        : "+f"(c[0]), "+f"(c[1]), "+f"(c[2]), "+f"(c[3])
        : "r"(a0), "r"(a1), "r"(a2), "r"(a3), "r"(b0), "r"(b1));
}
// pair tanh via f16x2 MUFU
__device__ __forceinline__ float2 tanh2(float x0, float x1){
    uint32_t h2, t2;
    asm("cvt.rn.f16x2.f32 %0, %1, %2;" : "=r"(h2) : "f"(x1), "f"(x0));
    asm("tanh.approx.f16x2 %0, %1;" : "=r"(t2) : "r"(h2));
    float r0, r1;
    asm("{.reg .b16 l, h;\n mov.b32 {l, h}, %2;\n cvt.f32.f16 %0, l;\n cvt.f32.f16 %1, h;}"
        : "=f"(r0), "=f"(r1) : "r"(t2));
    return make_float2(r0, r1);
}

// ---------------- SMEM layout ----------------
// k32 stage = [A0 4K][A1 4K][B0 4K][B1 4K] = 16384 B; 32B rows with 16B-chunk
// XOR swizzle: chunk c of row r stored at c ^ ((r>>2)&1). 4 stages.
#define STAGE_SZ 16384
#define OB       8192
#define O_RED    65536
#define SMEM_BYTES 74240     // 4*16384 + 128*17*4

// ---------------------------------------------------------------------------
// fp32 -> fp16 straight convert (standard [row][k] layout)
// ---------------------------------------------------------------------------
__global__ void conv_half(const float* __restrict__ src, __half* __restrict__ dst){
    int t = blockIdx.x * 256 + threadIdx.x;
    int w = t & 63;             // k16 window
    int m = t >> 6;             // row
    const float* p = src + (size_t)m*HH + w*16;
    float4 x0 = *(const float4*)(p);
    float4 x1 = *(const float4*)(p + 4);
    float4 x2 = *(const float4*)(p + 8);
    float4 x3 = *(const float4*)(p + 12);
    uint32_t o[8];
    __half2 h;
    h = __floats2half2_rn(x0.x, x0.y); o[0] = *(uint32_t*)&h;
    h = __floats2half2_rn(x0.z, x0.w); o[1] = *(uint32_t*)&h;
    h = __floats2half2_rn(x1.x, x1.y); o[2] = *(uint32_t*)&h;
    h = __floats2half2_rn(x1.z, x1.w); o[3] = *(uint32_t*)&h;
    h = __floats2half2_rn(x2.x, x2.y); o[4] = *(uint32_t*)&h;
    h = __floats2half2_rn(x2.z, x2.w); o[5] = *(uint32_t*)&h;
    h = __floats2half2_rn(x3.x, x3.y); o[6] = *(uint32_t*)&h;
    h = __floats2half2_rn(x3.z, x3.w); o[7] = *(uint32_t*)&h;
    uint4* d = (uint4*)(dst + (size_t)m*HH + w*16);
    d[0] = make_uint4(o[0], o[1], o[2], o[3]);
    d[1] = make_uint4(o[4], o[5], o[6], o[7]);
}

// ---------------------------------------------------------------------------
// pstP[np*32+b] = (pst[2np][b], pst[2np+1][b]); exact fp32
// ---------------------------------------------------------------------------
__global__ void pstT_kernel(const float* __restrict__ state, const float* __restrict__ w2,
                            const float* __restrict__ w1b, const float* __restrict__ w2b){
    int gw = (blockIdx.x * blockDim.x + threadIdx.x) >> 5;
    int lane = threadIdx.x & 31;
    if (gw >= (HH/2)*(BB/2)) return;
    int np = gw >> 4;
    int b0 = (gw & 15) * 2;
    int n0 = np * 2;
    const float* w0 = w2 + (size_t)n0 * HH;
    const float* w1r = w2 + (size_t)(n0+1) * HH;
    const float* s0 = state + b0*HH;
    const float* s1 = state + (b0+1)*HH;
    float a00=0.f, a01=0.f, a10=0.f, a11=0.f;
    #pragma unroll 4
    for (int h = lane; h < HH; h += 32){
        float x0 = s0[h], x1 = s1[h];
        float u = w0[h], w = w1r[h];
        a00 += u*x0; a01 += u*x1;
        a10 += w*x0; a11 += w*x1;
    }
    #pragma unroll
    for (int o = 16; o; o >>= 1){
        a00 += __shfl_xor_sync(~0u, a00, o);
        a01 += __shfl_xor_sync(~0u, a01, o);
        a10 += __shfl_xor_sync(~0u, a10, o);
        a11 += __shfl_xor_sync(~0u, a11, o);
    }
    if (lane == 0){
        float bias0 = w1b[n0] + w2b[n0];
        float bias1 = w1b[n0+1] + w2b[n0+1];
        g_pstP[np*BB + b0]   = make_float2(a00 + bias0, a10 + bias1);
        g_pstP[np*BB + b0+1] = make_float2(a01 + bias0, a11 + bias1);
    }
}

// ---------------------------------------------------------------------------
// cp.async one k32 stage with XOR swizzle: chunk c of row r -> c ^ ((r>>2)&1)
// ---------------------------------------------------------------------------
__device__ __forceinline__ void cp_stage(uint32_t sb, int m0, int s, int tid){
    int slot = s & 3;
    int kt = s & 31;
    int n0 = (s >> 5) << 7;
    uint32_t base = sb + slot*STAGE_SZ;
    int row = tid >> 1, c = tid & 1;
    int cs = c ^ ((row >> 2) & 1);           // swizzled chunk
    const __half* asrc = g_ah + (size_t)(m0 + row)*HH + kt*32 + c*8;
    const __half* bsrc = g_bh + (size_t)(n0 + row)*HH + kt*32 + c*8;
    uint32_t adst = base + row*32 + cs*16;
    uint32_t bdst = base + OB + row*32 + cs*16;
    cp16(adst,        asrc);
    cp16(adst + 4096, asrc + 16);
    cp16(bdst,        bsrc);
    cp16(bdst + 4096, bsrc + 16);
    cp_commit();
}

// ---------------------------------------------------------------------------
// fused fp16 GEMM + tanh + v-dot
// CTA 128M x (8 x 128N); 8 warps (2M x 4N), warp tile 64x32, k32 macro-stages.
// Fragments via ldmatrix.x4 on swizzled layout -> conflict-free phases.
// ---------------------------------------------------------------------------
__global__ void __launch_bounds__(256, 2)
gemm_score(const float* __restrict__ v){
    extern __shared__ __align__(128) char smem[];
    uint32_t sb = smem_u32(smem);
    const int tid  = threadIdx.x;
    const int lane = tid & 31;
    const int wid  = tid >> 5;
    const int wm   = wid & 1;       // 2 M-bands of 64
    const int wn   = wid >> 1;      // 4 N-bands of 32
    const int m0   = blockIdx.x * 128;
    const int hsel = wid & 1;       // stagger: odd warps do half1 first

    float* red = (float*)(smem + O_RED);
    for (int i = tid; i < 128*17; i += 256) red[i] = 0.f;
    __syncthreads();

    // per-lane ldmatrix byte offsets with swizzle (constant per lane):
    // A: row ra = (lane&15) [+ wm*64 + mf*16, both multiples of 16 -> no swizzle effect]
    //    chunk = (lane>>4) ^ ((ra>>2)&1) = (lane>>4) ^ ((lane>>2)&1)
    const uint32_t aoff = (uint32_t)(wm*2048 + (lane&15)*32
                          + (((lane>>4) ^ ((lane>>2)&1)) & 1)*16);
    // B: row rb = (lane&7) + ((lane>>4)&1)*8 [+ wn*32, multiple of 16]
    //    chunk = ((lane>>3)&1) ^ ((rb>>2)&1) = ((lane>>3)&1) ^ ((lane>>2)&1)
    const uint32_t boff = (uint32_t)(wn*1024 + ((lane&7) + ((lane>>4)&1)*8)*32
                          + ((((lane>>3) ^ (lane>>2)) & 1))*16);

    float acc[4][4][4];
    #pragma unroll
    for (int a = 0; a < 4; a++)
        #pragma unroll
        for (int b = 0; b < 4; b++)
            #pragma unroll
            for (int c = 0; c < 4; c++) acc[a][b][c] = 0.f;

    cp_stage(sb, m0, 0, tid);
    cp_stage(sb, m0, 1, tid);
    cp_stage(sb, m0, 2, tid);

    for (int s = 0; s < 256; ++s){
        if (s < 253) cp_wait2(); else cp_wait0();
        __syncthreads();
        if (s + 3 < 256) cp_stage(sb, m0, s + 3, tid);

        uint32_t st = sb + (s&3)*STAGE_SZ;
        uint32_t sA0 = st + hsel*4096;
        uint32_t sB0 = st + OB + hsel*4096;
        uint32_t sA1 = st + (hsel^1)*4096;
        uint32_t sB1 = st + OB + (hsel^1)*4096;

        // ---- load ALL fragments for both halves via ldmatrix ----
        uint32_t A0[4][4], A1[4][4], B0[8], B1[8];
        ldsm4(B0,     sB0 + boff);         // nf0 b0,b1, nf1 b0,b1
        ldsm4(B0 + 4, sB0 + boff + 512);   // nf2, nf3
        #pragma unroll
        for (int mf = 0; mf < 4; ++mf)
            ldsm4(A0[mf], sA0 + aoff + mf*512);
        ldsm4(B1,     sB1 + boff);
        ldsm4(B1 + 4, sB1 + boff + 512);
        #pragma unroll
        for (int mf = 0; mf < 4; ++mf)
            ldsm4(A1[mf], sA1 + aoff + mf*512);

        // ---- 32 back-to-back MMAs ----
        #pragma unroll
        for (int mf = 0; mf < 4; ++mf)
            #pragma unroll
            for (int nf = 0; nf < 4; ++nf)
                mma_f16(acc[mf][nf], A0[mf][0], A0[mf][1], A0[mf][2], A0[mf][3],
                        B0[nf*2], B0[nf*2+1]);
        #pragma unroll
        for (int mf = 0; mf < 4; ++mf)
            #pragma unroll
            for (int nf = 0; nf < 4; ++nf)
                mma_f16(acc[mf][nf], A1[mf][0], A1[mf][1], A1[mf][2], A1[mf][3],
                        B1[nf*2], B1[nf*2+1]);

        if ((s & 31) == 31){
            // epilogue for nt = s>>5 (N columns n0t..n0t+127)
            int n0t = (s >> 5) << 7;
            int npb = (n0t >> 1) + wn*16 + (lane&3);
            float2 vp[4], pstr[4][4];                   // pstr[bg][nf]
            #pragma unroll
            for (int nf = 0; nf < 4; ++nf){
                int np = npb + nf*4;
                vp[nf] = *(const float2*)(v + np*2);
                #pragma unroll
                for (int bg = 0; bg < 4; ++bg){
                    int b = (lane>>2) + bg*8;
                    pstr[bg][nf] = __ldg(&g_pstP[np*BB + b]);
                }
            }
            #pragma unroll
            for (int mf = 0; mf < 4; ++mf){
                #pragma unroll
                for (int half = 0; half < 2; ++half){
                    int row = wm*64 + mf*16 + (lane>>2) + half*8;
                    int bg  = (mf&1)*2 + half;
                    float sacc = 0.f;
                    #pragma unroll
                    for (int nf = 0; nf < 4; ++nf){
                        float x0 = acc[mf][nf][half*2 + 0] + pstr[bg][nf].x;
                        float x1 = acc[mf][nf][half*2 + 1] + pstr[bg][nf].y;
                        float2 t = tanh2(x0, x1);
                        sacc = fmaf(vp[nf].x, t.x, fmaf(vp[nf].y, t.y, sacc));
                    }
                    red[row*17 + wn*4 + (lane&3)] += sacc;
                }
            }
            #pragma unroll
            for (int a = 0; a < 4; a++)
                #pragma unroll
                for (int b = 0; b < 4; b++)
                    #pragma unroll
                    for (int c = 0; c < 4; c++) acc[a][b][c] = 0.f;
        }
    }

    __syncthreads();
    if (tid < 128){
        const float* r = red + tid*17;
        float s = 0.f;
        #pragma unroll
        for (int j = 0; j < 16; ++j) s += r[j];
        g_score[m0 + tid] = s;
    }
}

// ---------------------------------------------------------------------------
// softmax over L per batch column b; weights -> out + B*H, layout [l*B+b]
// ---------------------------------------------------------------------------
__global__ void softmax_kernel(float* __restrict__ out){
    __shared__ float sdata[256];
    int b = blockIdx.x;
    int tid = threadIdx.x;

    float mx = -1e30f;
    for (int l = tid; l < LL; l += 256) mx = fmaxf(mx, g_score[l*BB + b]);
    sdata[tid] = mx; __syncthreads();
    for (int s = 128; s > 0; s >>= 1){ if (tid < s) sdata[tid] = fmaxf(sdata[tid], sdata[tid+s]); __syncthreads(); }
    mx = sdata[0]; __syncthreads();

    float sum = 0.f;
    for (int l = tid; l < LL; l += 256) sum += __expf(g_score[l*BB + b] - mx);
    sdata[tid] = sum; __syncthreads();
    for (int s = 128; s > 0; s >>= 1){ if (tid < s) sdata[tid] += sdata[tid+s]; __syncthreads(); }
    float inv = 1.f / sdata[0];

    float* w = out + BB*HH;
    for (int l = tid; l < LL; l += 256)
        w[l*BB + b] = __expf(g_score[l*BB + b] - mx) * inv;
}

// ---------------------------------------------------------------------------
// context: 32-way L-split partials, then reduce; float4 over H
// ---------------------------------------------------------------------------
__global__ void ctx_part(const float* __restrict__ enc, const float* __restrict__ wts){
    int s = blockIdx.x;
    int b = blockIdx.y;
    int t = threadIdx.x;
    const float4* e = (const float4*)enc;
    float4 acc = make_float4(0.f, 0.f, 0.f, 0.f);
    int l0 = s * 64;
    #pragma unroll 4
    for (int l = 0; l < 64; ++l){
        float w = wts[(l0 + l)*BB + b];
        float4 x = e[((size_t)(l0 + l)*BB + b)*256 + t];
        acc.x += w*x.x; acc.y += w*x.y; acc.z += w*x.z; acc.w += w*x.w;
    }
    ((float4*)g_cpart)[((size_t)s*BB + b)*256 + t] = acc;
}
__global__ void ctx_reduce(float* __restrict__ out){
    int b = blockIdx.x;
    int t = threadIdx.x;
    float4 acc = make_float4(0.f, 0.f, 0.f, 0.f);
    #pragma unroll
    for (int s = 0; s < 32; ++s){
        float4 x = ((const float4*)g_cpart)[((size_t)s*BB + b)*256 + t];
        acc.x += x.x; acc.y += x.y; acc.z += x.z; acc.w += x.w;
    }
    ((float4*)out)[b*256 + t] = acc;
}

// ---------------------------------------------------------------------------
// launch: out = [context (B*H) | att_weights (L*B)]
// ---------------------------------------------------------------------------
extern "C" void kernel_launch(void* const* d_in, const int* in_sizes, int n_in,
                              void* d_out, int out_size) {
    const float* enc = (const float*)d_in[0];
    const float* lds = (const float*)d_in[1];   // state = first B*H floats
    const float* w1w = (const float*)d_in[2];
    const float* w1b = (const float*)d_in[3];
    const float* w2w = (const float*)d_in[4];
    const float* w2b = (const float*)d_in[5];
    const float* vw  = (const float*)d_in[6];
    // v_b cancels under softmax

    float* out = (float*)d_out;

    static bool attr_set = false;
    if (!attr_set){
        cudaFuncSetAttribute(gemm_score, cudaFuncAttributeMaxDynamicSharedMemorySize, SMEM_BYTES);
        attr_set = true;
    }

    __half *ah, *bh;
    cudaGetSymbolAddress((void**)&ah, g_ah);
    cudaGetSymbolAddress((void**)&bh, g_bh);

    conv_half<<<MM*64/256, 256>>>(enc, ah);
    conv_half<<<HH*64/256, 256>>>(w1w, bh);
    pstT_kernel<<<(HH/2)*(BB/2)/8, 256>>>(lds, w2w, w1b, w2b);
    gemm_score<<<MM/128, 256, SMEM_BYTES>>>(vw);
    softmax_kernel<<<BB, 256>>>(out);
    ctx_part<<<dim3(32, BB), 256>>>(enc, out + BB*HH);
    ctx_reduce<<<BB, 256>>>(out);
}

// round 16
// speedup vs baseline: 1.9839x; 1.0116x over previous
#include <cuda_runtime.h>
#include <cuda_fp16.h>
#include <cstdint>

#define LL 2048
#define BB 32
#define HH 1024
#define MM (LL*BB)

// ---------------- device scratch ----------------
__device__ __half g_ah[(size_t)MM*HH];   // enc fp16 (standard layout)
__device__ __half g_bh[(size_t)HH*HH];   // w1 fp16
__device__ float2 g_pstP[(HH/2)*BB];     // (pst[2np][b], pst[2np+1][b]), bias folded
__device__ float g_score[MM];            // scores [l*B+b]
__device__ float g_cpart[32*BB*HH];      // context partials

// ---------------- PTX helpers ----------------
__device__ __forceinline__ uint32_t smem_u32(const void* p){
    uint32_t a;
    asm("{ .reg .u64 t; cvta.to.shared.u64 t, %1; cvt.u32.u64 %0, t; }" : "=r"(a) : "l"(p));
    return a;
}
__device__ __forceinline__ void cp16(uint32_t dst, const void* src){
    asm volatile("cp.async.ca.shared.global [%0], [%1], 16;" :: "r"(dst), "l"(src));
}
__device__ __forceinline__ void cp_commit(){ asm volatile("cp.async.commit_group;" ::: "memory"); }
__device__ __forceinline__ void cp_wait2(){ asm volatile("cp.async.wait_group 2;" ::: "memory"); }
__device__ __forceinline__ void cp_wait0(){ asm volatile("cp.async.wait_group 0;" ::: "memory"); }
__device__ __forceinline__ void ldsm4(uint32_t* r, uint32_t addr){
    asm volatile("ldmatrix.sync.aligned.m8n8.x4.shared.b16 {%0,%1,%2,%3}, [%4];"
        : "=r"(r[0]), "=r"(r[1]), "=r"(r[2]), "=r"(r[3]) : "r"(addr));
}
__device__ __forceinline__ void mma_f16(float* c, uint32_t a0, uint32_t a1, uint32_t a2, uint32_t a3,
                                        uint32_t b0, uint32_t b1){
    asm volatile("mma.sync.aligned.m16n8k16.row.col.f32.f16.f16.f32 "
        "{%0,%1,%2,%3}, {%4,%5,%6,%7}, {%8,%9}, {%0,%1,%2,%3};"
        : "+f"(c[0]), "+f"(c[1]), "+f"(c[2]), "+f"(c[3])
        : "r"(a0), "r"(a1), "r"(a2), "r"(a3), "r"(b0), "r"(b1));
}
// pair tanh via f16x2 MUFU
__device__ __forceinline__ float2 tanh2(float x0, float x1){
    uint32_t h2, t2;
    asm("cvt.rn.f16x2.f32 %0, %1, %2;" : "=r"(h2) : "f"(x1), "f"(x0));
    asm("tanh.approx.f16x2 %0, %1;" : "=r"(t2) : "r"(h2));
    float r0, r1;
    asm("{.reg .b16 l, h;\n mov.b32 {l, h}, %2;\n cvt.f32.f16 %0, l;\n cvt.f32.f16 %1, h;}"
        : "=f"(r0), "=f"(r1) : "r"(t2));
    return make_float2(r0, r1);
}

// ---------------- SMEM layout ----------------
// k32 stage = [A0 4K][A1 4K][B0 8K][B1 8K] = 24576 B; 32B rows with 16B-chunk
// XOR swizzle: chunk c of row r stored at c ^ ((r>>2)&1). 4 stages.
#define STAGE_SZ 24576
#define OB       8192
#define O_RED    98304
#define SMEM_BYTES 107008    // 4*24576 + 128*17*4

// ---------------------------------------------------------------------------
// fp32 -> fp16 straight convert (standard [row][k] layout)
// ---------------------------------------------------------------------------
__global__ void conv_half(const float* __restrict__ src, __half* __restrict__ dst){
    int t = blockIdx.x * 256 + threadIdx.x;
    int w = t & 63;             // k16 window
    int m = t >> 6;             // row
    const float* p = src + (size_t)m*HH + w*16;
    float4 x0 = *(const float4*)(p);
    float4 x1 = *(const float4*)(p + 4);
    float4 x2 = *(const float4*)(p + 8);
    float4 x3 = *(const float4*)(p + 12);
    uint32_t o[8];
    __half2 h;
    h = __floats2half2_rn(x0.x, x0.y); o[0] = *(uint32_t*)&h;
    h = __floats2half2_rn(x0.z, x0.w); o[1] = *(uint32_t*)&h;
    h = __floats2half2_rn(x1.x, x1.y); o[2] = *(uint32_t*)&h;
    h = __floats2half2_rn(x1.z, x1.w); o[3] = *(uint32_t*)&h;
    h = __floats2half2_rn(x2.x, x2.y); o[4] = *(uint32_t*)&h;
    h = __floats2half2_rn(x2.z, x2.w); o[5] = *(uint32_t*)&h;
    h = __floats2half2_rn(x3.x, x3.y); o[6] = *(uint32_t*)&h;
    h = __floats2half2_rn(x3.z, x3.w); o[7] = *(uint32_t*)&h;
    uint4* d = (uint4*)(dst + (size_t)m*HH + w*16);
    d[0] = make_uint4(o[0], o[1], o[2], o[3]);
    d[1] = make_uint4(o[4], o[5], o[6], o[7]);
}

// ---------------------------------------------------------------------------
// pstP[np*32+b] = (pst[2np][b], pst[2np+1][b]); exact fp32
// ---------------------------------------------------------------------------
__global__ void pstT_kernel(const float* __restrict__ state, const float* __restrict__ w2,
                            const float* __restrict__ w1b, const float* __restrict__ w2b){
    int gw = (blockIdx.x * blockDim.x + threadIdx.x) >> 5;
    int lane = threadIdx.x & 31;
    if (gw >= (HH/2)*(BB/2)) return;
    int np = gw >> 4;
    int b0 = (gw & 15) * 2;
    int n0 = np * 2;
    const float* w0 = w2 + (size_t)n0 * HH;
    const float* w1r = w2 + (size_t)(n0+1) * HH;
    const float* s0 = state + b0*HH;
    const float* s1 = state + (b0+1)*HH;
    float a00=0.f, a01=0.f, a10=0.f, a11=0.f;
    #pragma unroll 4
    for (int h = lane; h < HH; h += 32){
        float x0 = s0[h], x1 = s1[h];
        float u = w0[h], w = w1r[h];
        a00 += u*x0; a01 += u*x1;
        a10 += w*x0; a11 += w*x1;
    }
    #pragma unroll
    for (int o = 16; o; o >>= 1){
        a00 += __shfl_xor_sync(~0u, a00, o);
        a01 += __shfl_xor_sync(~0u, a01, o);
        a10 += __shfl_xor_sync(~0u, a10, o);
        a11 += __shfl_xor_sync(~0u, a11, o);
    }
    if (lane == 0){
        float bias0 = w1b[n0] + w2b[n0];
        float bias1 = w1b[n0+1] + w2b[n0+1];
        g_pstP[np*BB + b0]   = make_float2(a00 + bias0, a10 + bias1);
        g_pstP[np*BB + b0+1] = make_float2(a01 + bias0, a11 + bias1);
    }
}

// ---------------------------------------------------------------------------
// cp.async one k32 stage: A 128 rows + B 256 rows, 2 k16 subtiles each,
// XOR swizzle (chunk c of row r -> c ^ ((r>>2)&1)). 6 cp16 per thread.
// s encodes (nt, kt): kt = s & 31, n0 = (s>>5)*256. 128 stages total.
// ---------------------------------------------------------------------------
__device__ __forceinline__ void cp_stage(uint32_t sb, int m0, int s, int tid){
    int slot = s & 3;
    int kt = s & 31;
    int n0 = (s >> 5) << 8;
    uint32_t base = sb + slot*STAGE_SZ;
    int row = tid >> 1, c = tid & 1;
    int cs = c ^ ((row >> 2) & 1);
    // A (128 rows)
    const __half* asrc = g_ah + (size_t)(m0 + row)*HH + kt*32 + c*8;
    uint32_t adst = base + row*32 + cs*16;
    cp16(adst,        asrc);
    cp16(adst + 4096, asrc + 16);
    // B rows row and row+128
    const __half* bsrc0 = g_bh + (size_t)(n0 + row)*HH + kt*32 + c*8;
    uint32_t bdst0 = base + OB + row*32 + cs*16;
    cp16(bdst0,        bsrc0);
    cp16(bdst0 + 8192, bsrc0 + 16);
    int row2 = row + 128;
    int cs2 = c ^ ((row2 >> 2) & 1);
    const __half* bsrc1 = g_bh + (size_t)(n0 + row2)*HH + kt*32 + c*8;
    uint32_t bdst1 = base + OB + row2*32 + cs2*16;
    cp16(bdst1,        bsrc1);
    cp16(bdst1 + 8192, bsrc1 + 16);
    cp_commit();
}

// ---------------------------------------------------------------------------
// fused fp16 GEMM + tanh + v-dot
// CTA 128M x 256N, 8 warps (2M x 4N), warp tile 64x64, occupancy 1.
// 128 k32 macro-stages (4 nt x 32 kt). 64 MMAs per warp per stage.
// bytes/MMA = 128 frag + 47 cp -> crossbar no longer the binder.
// ---------------------------------------------------------------------------
__global__ void __launch_bounds__(256, 1)
gemm_score(const float* __restrict__ v){
    extern __shared__ __align__(128) char smem[];
    uint32_t sb = smem_u32(smem);
    const int tid  = threadIdx.x;
    const int lane = tid & 31;
    const int wid  = tid >> 5;
    const int wm   = wid & 1;       // 2 M-bands of 64
    const int wn   = wid >> 1;      // 4 N-bands of 64
    const int m0   = blockIdx.x * 128;
    const int hsel = wid & 1;       // stagger: odd warps do half1 first

    float* red = (float*)(smem + O_RED);
    for (int i = tid; i < 128*17; i += 256) red[i] = 0.f;
    __syncthreads();

    // per-lane ldmatrix byte offsets with swizzle (constant per lane)
    const uint32_t aoff = (uint32_t)(wm*2048 + (lane&15)*32
                          + (((lane>>4) ^ ((lane>>2)&1)) & 1)*16);
    const uint32_t boff = (uint32_t)(wn*2048 + ((lane&7) + ((lane>>4)&1)*8)*32
                          + ((((lane>>3) ^ (lane>>2)) & 1))*16);

    float acc[4][8][4];
    #pragma unroll
    for (int a = 0; a < 4; a++)
        #pragma unroll
        for (int b = 0; b < 8; b++)
            #pragma unroll
            for (int c = 0; c < 4; c++) acc[a][b][c] = 0.f;

    cp_stage(sb, m0, 0, tid);
    cp_stage(sb, m0, 1, tid);
    cp_stage(sb, m0, 2, tid);

    for (int s = 0; s < 128; ++s){
        if (s < 125) cp_wait2(); else cp_wait0();
        __syncthreads();
        if (s + 3 < 128) cp_stage(sb, m0, s + 3, tid);

        uint32_t st = sb + (s&3)*STAGE_SZ;
        uint32_t sA0 = st + hsel*4096;
        uint32_t sA1 = st + (hsel^1)*4096;
        uint32_t sB0 = st + OB + hsel*8192;
        uint32_t sB1 = st + OB + (hsel^1)*8192;

        // ---- fragments for both k16 halves via ldmatrix ----
        uint32_t A0[4][4], A1[4][4], B0[16], B1[16];
        #pragma unroll
        for (int nb = 0; nb < 4; ++nb)
            ldsm4(B0 + nb*4, sB0 + boff + nb*512);
        #pragma unroll
        for (int mf = 0; mf < 4; ++mf)
            ldsm4(A0[mf], sA0 + aoff + mf*512);
        #pragma unroll
        for (int nb = 0; nb < 4; ++nb)
            ldsm4(B1 + nb*4, sB1 + boff + nb*512);
        #pragma unroll
        for (int mf = 0; mf < 4; ++mf)
            ldsm4(A1[mf], sA1 + aoff + mf*512);

        // ---- 64 back-to-back MMAs ----
        #pragma unroll
        for (int mf = 0; mf < 4; ++mf)
            #pragma unroll
            for (int nf = 0; nf < 8; ++nf)
                mma_f16(acc[mf][nf], A0[mf][0], A0[mf][1], A0[mf][2], A0[mf][3],
                        B0[nf*2], B0[nf*2+1]);
        #pragma unroll
        for (int mf = 0; mf < 4; ++mf)
            #pragma unroll
            for (int nf = 0; nf < 8; ++nf)
                mma_f16(acc[mf][nf], A1[mf][0], A1[mf][1], A1[mf][2], A1[mf][3],
                        B1[nf*2], B1[nf*2+1]);

        if ((s & 31) == 31){
            // epilogue for nt = s>>5 (256 N columns); 2 chunks of 4 n8-blocks
            int n0t = (s >> 5) << 8;
            #pragma unroll
            for (int nfc = 0; nfc < 2; ++nfc){
                int npb = (n0t >> 1) + wn*32 + nfc*16 + (lane&3);
                float2 vp[4], pstr[4][4];               // pstr[bg][nf2]
                #pragma unroll
                for (int nf2 = 0; nf2 < 4; ++nf2){
                    int np = npb + nf2*4;
                    vp[nf2] = *(const float2*)(v + np*2);
                    #pragma unroll
                    for (int bg = 0; bg < 4; ++bg){
                        int b = (lane>>2) + bg*8;
                        pstr[bg][nf2] = __ldg(&g_pstP[np*BB + b]);
                    }
                }
                #pragma unroll
                for (int mf = 0; mf < 4; ++mf){
                    #pragma unroll
                    for (int half = 0; half < 2; ++half){
                        int row = wm*64 + mf*16 + (lane>>2) + half*8;
                        int bg  = (mf&1)*2 + half;
                        float sacc = 0.f;
                        #pragma unroll
                        for (int nf2 = 0; nf2 < 4; ++nf2){
                            int nf = nfc*4 + nf2;
                            float x0 = acc[mf][nf][half*2 + 0] + pstr[bg][nf2].x;
                            float x1 = acc[mf][nf][half*2 + 1] + pstr[bg][nf2].y;
                            float2 t = tanh2(x0, x1);
                            sacc = fmaf(vp[nf2].x, t.x, fmaf(vp[nf2].y, t.y, sacc));
                        }
                        red[row*17 + wn*4 + (lane&3)] += sacc;
                    }
                }
            }
            #pragma unroll
            for (int a = 0; a < 4; a++)
                #pragma unroll
                for (int b = 0; b < 8; b++)
                    #pragma unroll
                    for (int c = 0; c < 4; c++) acc[a][b][c] = 0.f;
        }
    }

    __syncthreads();
    if (tid < 128){
        const float* r = red + tid*17;
        float s = 0.f;
        #pragma unroll
        for (int j = 0; j < 16; ++j) s += r[j];
        g_score[m0 + tid] = s;
    }
}

// ---------------------------------------------------------------------------
// softmax over L per batch column b; weights -> out + B*H, layout [l*B+b]
// ---------------------------------------------------------------------------
__global__ void softmax_kernel(float* __restrict__ out){
    __shared__ float sdata[256];
    int b = blockIdx.x;
    int tid = threadIdx.x;

    float mx = -1e30f;
    for (int l = tid; l < LL; l += 256) mx = fmaxf(mx, g_score[l*BB + b]);
    sdata[tid] = mx; __syncthreads();
    for (int s = 128; s > 0; s >>= 1){ if (tid < s) sdata[tid] = fmaxf(sdata[tid], sdata[tid+s]); __syncthreads(); }
    mx = sdata[0]; __syncthreads();

    float sum = 0.f;
    for (int l = tid; l < LL; l += 256) sum += __expf(g_score[l*BB + b] - mx);
    sdata[tid] = sum; __syncthreads();
    for (int s = 128; s > 0; s >>= 1){ if (tid < s) sdata[tid] += sdata[tid+s]; __syncthreads(); }
    float inv = 1.f / sdata[0];

    float* w = out + BB*HH;
    for (int l = tid; l < LL; l += 256)
        w[l*BB + b] = __expf(g_score[l*BB + b] - mx) * inv;
}

// ---------------------------------------------------------------------------
// context: 32-way L-split partials, then reduce; float4 over H
// ---------------------------------------------------------------------------
__global__ void ctx_part(const float* __restrict__ enc, const float* __restrict__ wts){
    int s = blockIdx.x;
    int b = blockIdx.y;
    int t = threadIdx.x;
    const float4* e = (const float4*)enc;
    float4 acc = make_float4(0.f, 0.f, 0.f, 0.f);
    int l0 = s * 64;
    #pragma unroll 4
    for (int l = 0; l < 64; ++l){
        float w = wts[(l0 + l)*BB + b];
        float4 x = e[((size_t)(l0 + l)*BB + b)*256 + t];
        acc.x += w*x.x; acc.y += w*x.y; acc.z += w*x.z; acc.w += w*x.w;
    }
    ((float4*)g_cpart)[((size_t)s*BB + b)*256 + t] = acc;
}
__global__ void ctx_reduce(float* __restrict__ out){
    int b = blockIdx.x;
    int t = threadIdx.x;
    float4 acc = make_float4(0.f, 0.f, 0.f, 0.f);
    #pragma unroll
    for (int s = 0; s < 32; ++s){
        float4 x = ((const float4*)g_cpart)[((size_t)s*BB + b)*256 + t];
        acc.x += x.x; acc.y += x.y; acc.z += x.z; acc.w += x.w;
    }
    ((float4*)out)[b*256 + t] = acc;
}

// ---------------------------------------------------------------------------
// launch: out = [context (B*H) | att_weights (L*B)]
// ---------------------------------------------------------------------------
extern "C" void kernel_launch(void* const* d_in, const int* in_sizes, int n_in,
                              void* d_out, int out_size) {
    const float* enc = (const float*)d_in[0];
    const float* lds = (const float*)d_in[1];   // state = first B*H floats
    const float* w1w = (const float*)d_in[2];
    const float* w1b = (const float*)d_in[3];
    const float* w2w = (const float*)d_in[4];
    const float* w2b = (const float*)d_in[5];
    const float* vw  = (const float*)d_in[6];
    // v_b cancels under softmax

    float* out = (float*)d_out;

    static bool attr_set = false;
    if (!attr_set){
        cudaFuncSetAttribute(gemm_score, cudaFuncAttributeMaxDynamicSharedMemorySize, SMEM_BYTES);
        attr_set = true;
    }

    __half *ah, *bh;
    cudaGetSymbolAddress((void**)&ah, g_ah);
    cudaGetSymbolAddress((void**)&bh, g_bh);

    conv_half<<<MM*64/256, 256>>>(enc, ah);
    conv_half<<<HH*64/256, 256>>>(w1w, bh);
    pstT_kernel<<<(HH/2)*(BB/2)/8, 256>>>(lds, w2w, w1b, w2b);
    gemm_score<<<MM/128, 256, SMEM_BYTES>>>(vw);
    softmax_kernel<<<BB, 256>>>(out);
    ctx_part<<<dim3(32, BB), 256>>>(enc, out + BB*HH);
    ctx_reduce<<<BB, 256>>>(out);
}